// round 2
// baseline (speedup 1.0000x reference)
#include <cuda_runtime.h>

// ---------------- problem constants ----------------
#define B_DIM   2
#define T_DIM   2048
#define DMODEL  1024
#define NHEAD   16
#define DKH     64
#define M_DIM   (B_DIM * T_DIM)      // 4096

// ---------------- scratch (device globals, no allocs) ----------------
__device__ float g_q[B_DIM * NHEAD * T_DIM * DKH];
__device__ float g_k[B_DIM * NHEAD * T_DIM * DKH];
__device__ float g_v[B_DIM * NHEAD * T_DIM * DKH];
__device__ float g_attn[B_DIM * T_DIM * DMODEL];

// ---------------- fast exp on the FMA pipe (avoid MUFU bottleneck) ----------------
// exp(x) = 2^(x*log2e); degree-6 Taylor of 2^f on [0,1): rel err ~6e-6
__device__ __forceinline__ float fexp(float x) {
    float y = x * 1.4426950408889634f;
    y = fmaxf(y, -120.0f);
    float n = floorf(y);
    float f = y - n;
    float p = 1.5403530393381606e-4f;
    p = fmaf(p, f, 1.3333558146428443e-3f);
    p = fmaf(p, f, 9.6181291076284771e-3f);
    p = fmaf(p, f, 5.5504108664821580e-2f);
    p = fmaf(p, f, 2.4022650695910071e-1f);
    p = fmaf(p, f, 6.9314718055994531e-1f);
    p = fmaf(p, f, 1.0f);
    int e = (int)n;
    float r = __int_as_float((e + 127) << 23);
    return p * r;
}

// ---------------- projection GEMM: Y[m,n] = sum_k A[m,k]*W[n,k] + b[n] ----------------
// A: [M, 1024] row-major, W: [1024, 1024] row-major (torch Linear => dot with W rows)
// BM=BN=128, BK=8, 256 threads, 8x8 micro-tile.
// PERMUTE=true: write into [B, H, T, dk] layout; else flat [M, DMODEL].
template <bool PERMUTE>
__global__ __launch_bounds__(256) void proj_kernel(
    const float* __restrict__ A, const float* __restrict__ W,
    const float* __restrict__ bias, float* __restrict__ out)
{
    __shared__ float As[8][132];
    __shared__ float Bs[8][132];

    const int tid = threadIdx.x;
    const int tx = tid & 15;          // 0..15 (n micro)
    const int ty = tid >> 4;          // 0..15 (m micro)
    const int m0 = blockIdx.y * 128;
    const int n0 = blockIdx.x * 128;
    const int row = tid >> 1;         // 0..127
    const int kq  = (tid & 1) * 4;    // 0 or 4

    float acc[8][8];
#pragma unroll
    for (int i = 0; i < 8; i++)
#pragma unroll
        for (int j = 0; j < 8; j++) acc[i][j] = 0.0f;

    for (int k0 = 0; k0 < DMODEL; k0 += 8) {
        float4 a4 = *(const float4*)&A[(size_t)(m0 + row) * DMODEL + k0 + kq];
        float4 b4 = *(const float4*)&W[(size_t)(n0 + row) * DMODEL + k0 + kq];
        __syncthreads();
        As[kq + 0][row] = a4.x; As[kq + 1][row] = a4.y;
        As[kq + 2][row] = a4.z; As[kq + 3][row] = a4.w;
        Bs[kq + 0][row] = b4.x; Bs[kq + 1][row] = b4.y;
        Bs[kq + 2][row] = b4.z; Bs[kq + 3][row] = b4.w;
        __syncthreads();
#pragma unroll
        for (int k = 0; k < 8; k++) {
            float4 a0 = *(const float4*)&As[k][ty * 8];
            float4 a1 = *(const float4*)&As[k][ty * 8 + 4];
            float4 b0 = *(const float4*)&Bs[k][tx * 8];
            float4 b1 = *(const float4*)&Bs[k][tx * 8 + 4];
            float av[8] = {a0.x, a0.y, a0.z, a0.w, a1.x, a1.y, a1.z, a1.w};
            float bv[8] = {b0.x, b0.y, b0.z, b0.w, b1.x, b1.y, b1.z, b1.w};
#pragma unroll
            for (int i = 0; i < 8; i++)
#pragma unroll
                for (int j = 0; j < 8; j++)
                    acc[i][j] = fmaf(av[i], bv[j], acc[i][j]);
        }
    }

#pragma unroll
    for (int i = 0; i < 8; i++) {
        int m = m0 + ty * 8 + i;
#pragma unroll
        for (int j = 0; j < 8; j++) {
            int n = n0 + tx * 8 + j;
            float v = acc[i][j] + bias[n];
            if (PERMUTE) {
                int b = m >> 11, t = m & (T_DIM - 1);
                int h = n >> 6,  d = n & 63;
                out[(((size_t)(b * NHEAD + h) * T_DIM + t) * DKH) + d] = v;
            } else {
                out[(size_t)m * DMODEL + n] = v;
            }
        }
    }
}

// ---------------- flash attention: per (q-tile 64, head, batch) ----------------
#define SM_PAD 68
#define FLASH_SMEM ((4 * 64 * SM_PAD + 3 * 64 + 256) * 4)

__global__ __launch_bounds__(256) void flash_kernel(
    const float* __restrict__ bias, float* __restrict__ Out)
{
    extern __shared__ float sm[];
    float* sQ  = sm;                     // [64][68]  d-major (transposed)
    float* sK  = sm + 1 * 64 * SM_PAD;   // [64][68]  d-major (transposed)
    float* sV  = sm + 2 * 64 * SM_PAD;   // [64][68]  n-major (natural)
    float* sS  = sm + 3 * 64 * SM_PAD;   // [64][68]  r-major
    float* m_s = sm + 4 * 64 * SM_PAD;   // [64]
    float* l_s = m_s + 64;               // [64]
    float* a_s = l_s + 64;               // [64]
    float* red = a_s + 64;               // [256]

    const int tid = threadIdx.x;
    const int tx = tid & 15;             // 0..15
    const int ty = tid >> 4;             // 0..15
    const int q0 = blockIdx.x * 64;
    const int h  = blockIdx.y;
    const int b  = blockIdx.z;
    const int bh = b * NHEAD + h;

    const float* Qp = g_q + (size_t)bh * T_DIM * DKH;
    const float* Kp = g_k + (size_t)bh * T_DIM * DKH;
    const float* Vp = g_v + (size_t)bh * T_DIM * DKH;
    const float* biasp = bias + (size_t)h * T_DIM * T_DIM;

    if (tid < 64) { m_s[tid] = -1e30f; l_s[tid] = 0.0f; }

    // load Q tile (transposed into sQ[d][r])
    {
        const int rbase = tid >> 4;
        const int d4 = (tid & 15) * 4;
#pragma unroll
        for (int i = 0; i < 4; i++) {
            int rr = rbase + i * 16;
            float4 q4 = *(const float4*)&Qp[(size_t)(q0 + rr) * DKH + d4];
            sQ[(d4 + 0) * SM_PAD + rr] = q4.x;
            sQ[(d4 + 1) * SM_PAD + rr] = q4.y;
            sQ[(d4 + 2) * SM_PAD + rr] = q4.z;
            sQ[(d4 + 3) * SM_PAD + rr] = q4.w;
        }
    }

    float o[4][4];
#pragma unroll
    for (int i = 0; i < 4; i++)
#pragma unroll
        for (int j = 0; j < 4; j++) o[i][j] = 0.0f;

    __syncthreads();

    const int row  = tid & 63;
    const int part = tid >> 6;

    for (int jt = 0; jt < T_DIM / 64; jt++) {
        const int k0 = jt * 64;

        // load K (transposed) and V (natural)
        {
            const int rbase = tid >> 4;
            const int d4 = (tid & 15) * 4;
#pragma unroll
            for (int i = 0; i < 4; i++) {
                int rr = rbase + i * 16;
                float4 kv = *(const float4*)&Kp[(size_t)(k0 + rr) * DKH + d4];
                sK[(d4 + 0) * SM_PAD + rr] = kv.x;
                sK[(d4 + 1) * SM_PAD + rr] = kv.y;
                sK[(d4 + 2) * SM_PAD + rr] = kv.z;
                sK[(d4 + 3) * SM_PAD + rr] = kv.w;
                float4 vv = *(const float4*)&Vp[(size_t)(k0 + rr) * DKH + d4];
                *(float4*)&sV[rr * SM_PAD + d4] = vv;
            }
        }
        __syncthreads();

        // S = Q @ K^T
        float acc[4][4];
#pragma unroll
        for (int i = 0; i < 4; i++)
#pragma unroll
            for (int j = 0; j < 4; j++) acc[i][j] = 0.0f;

#pragma unroll 16
        for (int d = 0; d < 64; d++) {
            float4 q4 = *(const float4*)&sQ[d * SM_PAD + ty * 4];
            float4 k4 = *(const float4*)&sK[d * SM_PAD + tx * 4];
            float qa[4] = {q4.x, q4.y, q4.z, q4.w};
            float kb[4] = {k4.x, k4.y, k4.z, k4.w};
#pragma unroll
            for (int i = 0; i < 4; i++)
#pragma unroll
                for (int j = 0; j < 4; j++)
                    acc[i][j] = fmaf(qa[i], kb[j], acc[i][j]);
        }

        // scale + bias, write S tile
#pragma unroll
        for (int i = 0; i < 4; i++) {
            int qrow = q0 + ty * 4 + i;
            float4 b4 = *(const float4*)&biasp[(size_t)qrow * T_DIM + k0 + tx * 4];
            float4 s4;
            s4.x = fmaf(acc[i][0], 0.125f, b4.x);
            s4.y = fmaf(acc[i][1], 0.125f, b4.y);
            s4.z = fmaf(acc[i][2], 0.125f, b4.z);
            s4.w = fmaf(acc[i][3], 0.125f, b4.w);
            *(float4*)&sS[(ty * 4 + i) * SM_PAD + tx * 4] = s4;
        }
        __syncthreads();

        // online softmax: 4 threads per row, 16 cols each
        float lmax = -1e30f;
#pragma unroll
        for (int q = 0; q < 16; q++)
            lmax = fmaxf(lmax, sS[row * SM_PAD + part * 16 + q]);
        red[row * 4 + part] = lmax;
        __syncthreads();
        float tm = fmaxf(fmaxf(red[row * 4 + 0], red[row * 4 + 1]),
                         fmaxf(red[row * 4 + 2], red[row * 4 + 3]));
        float mold = m_s[row];
        float newm = fmaxf(mold, tm);
        __syncthreads();  // everyone has read red before we overwrite it

        float lsum = 0.0f;
#pragma unroll
        for (int q = 0; q < 16; q++) {
            float p = fexp(sS[row * SM_PAD + part * 16 + q] - newm);
            sS[row * SM_PAD + part * 16 + q] = p;
            lsum += p;
        }
        red[row * 4 + part] = lsum;
        __syncthreads();

        if (tid < 64) {
            float ts = red[tid * 4 + 0] + red[tid * 4 + 1] +
                       red[tid * 4 + 2] + red[tid * 4 + 3];
            float alpha = fexp(mold - newm);
            l_s[tid] = l_s[tid] * alpha + ts;
            m_s[tid] = newm;
            a_s[tid] = alpha;
        }
        __syncthreads();

        // O = alpha*O + P @ V
        float ar[4];
#pragma unroll
        for (int i = 0; i < 4; i++) ar[i] = a_s[ty * 4 + i];
#pragma unroll
        for (int i = 0; i < 4; i++)
#pragma unroll
            for (int j = 0; j < 4; j++) o[i][j] *= ar[i];

#pragma unroll 16
        for (int n = 0; n < 64; n++) {
            float4 v4 = *(const float4*)&sV[n * SM_PAD + tx * 4];
            float vb[4] = {v4.x, v4.y, v4.z, v4.w};
            float pv[4];
#pragma unroll
            for (int i = 0; i < 4; i++) pv[i] = sS[(ty * 4 + i) * SM_PAD + n];
#pragma unroll
            for (int i = 0; i < 4; i++)
#pragma unroll
                for (int j = 0; j < 4; j++)
                    o[i][j] = fmaf(pv[i], vb[j], o[i][j]);
        }
        __syncthreads();  // protect sK/sV/sS before next tile load
    }

    // epilogue: O /= l, write to [B, T, D] layout (head-interleaved)
#pragma unroll
    for (int i = 0; i < 4; i++) {
        int r = ty * 4 + i;
        float inv = __fdividef(1.0f, l_s[r]);
        float4 w;
        w.x = o[i][0] * inv;
        w.y = o[i][1] * inv;
        w.z = o[i][2] * inv;
        w.w = o[i][3] * inv;
        *(float4*)&Out[((size_t)(b * T_DIM + q0 + r)) * DMODEL + h * DKH + tx * 4] = w;
    }
}

// ---------------- launch ----------------
extern "C" void kernel_launch(void* const* d_in, const int* in_sizes, int n_in,
                              void* d_out, int out_size)
{
    const float* x    = (const float*)d_in[0];
    const float* bias = (const float*)d_in[1];
    const float* Wq   = (const float*)d_in[2];
    const float* bq   = (const float*)d_in[3];
    const float* Wk   = (const float*)d_in[4];
    const float* bk   = (const float*)d_in[5];
    const float* Wv   = (const float*)d_in[6];
    const float* bv   = (const float*)d_in[7];
    const float* Wo   = (const float*)d_in[8];
    const float* bo   = (const float*)d_in[9];
    float* out = (float*)d_out;

    float *pq, *pk, *pv, *pa;
    cudaGetSymbolAddress((void**)&pq, g_q);
    cudaGetSymbolAddress((void**)&pk, g_k);
    cudaGetSymbolAddress((void**)&pv, g_v);
    cudaGetSymbolAddress((void**)&pa, g_attn);

    cudaFuncSetAttribute(flash_kernel,
                         cudaFuncAttributeMaxDynamicSharedMemorySize, FLASH_SMEM);

    dim3 gg(DMODEL / 128, M_DIM / 128);  // (8, 32)
    proj_kernel<true><<<gg, 256>>>(x, Wq, bq, pq);
    proj_kernel<true><<<gg, 256>>>(x, Wk, bk, pk);
    proj_kernel<true><<<gg, 256>>>(x, Wv, bv, pv);

    flash_kernel<<<dim3(T_DIM / 64, NHEAD, B_DIM), 256, FLASH_SMEM>>>(bias, pa);

    proj_kernel<false><<<gg, 256>>>(pa, Wo, bo, out);
}

// round 3
// speedup vs baseline: 2.1554x; 2.1554x over previous
#include <cuda_runtime.h>
#include <cuda_bf16.h>
#include <cstdint>

// ---------------- problem constants ----------------
#define B_DIM   2
#define T_DIM   2048
#define DMODEL  1024
#define NHEAD   16
#define DKH     64
#define M_DIM   (B_DIM * T_DIM)      // 4096
#define KDIM    DMODEL

// ---------------- scratch (device globals, no allocs) ----------------
// hi/lo bf16 splits
__device__ __nv_bfloat16 g_xhi[M_DIM * DMODEL], g_xlo[M_DIM * DMODEL];
__device__ __nv_bfloat16 g_whi[4 * DMODEL * DMODEL], g_wlo[4 * DMODEL * DMODEL];
__device__ __nv_bfloat16 g_qhi[M_DIM * DMODEL], g_qlo[M_DIM * DMODEL];   // [B,H,T,dk]
__device__ __nv_bfloat16 g_khi[M_DIM * DMODEL], g_klo[M_DIM * DMODEL];   // [B,H,T,dk]
__device__ __nv_bfloat16 g_vhi[M_DIM * DMODEL], g_vlo[M_DIM * DMODEL];   // [B,H,dk,T] (transposed!)
__device__ __nv_bfloat16 g_ahi[M_DIM * DMODEL], g_alo[M_DIM * DMODEL];   // [B,T,D]

// ---------------- helpers ----------------
__device__ __forceinline__ unsigned short bf2u(__nv_bfloat16 h) {
    return *reinterpret_cast<unsigned short*>(&h);
}

// split two floats into packed bf16 hi and bf16 lo (residual)
__device__ __forceinline__ void split2(float a, float b, uint32_t& hi, uint32_t& lo) {
    __nv_bfloat16 ha = __float2bfloat16_rn(a), hb = __float2bfloat16_rn(b);
    float ra = a - __bfloat162float(ha), rb = b - __bfloat162float(hb);
    __nv_bfloat16 la = __float2bfloat16_rn(ra), lb = __float2bfloat16_rn(rb);
    hi = ((uint32_t)bf2u(hb) << 16) | (uint32_t)bf2u(ha);
    lo = ((uint32_t)bf2u(lb) << 16) | (uint32_t)bf2u(la);
}

// fast exp on the FMA pipe
__device__ __forceinline__ float fexp(float x) {
    float y = x * 1.4426950408889634f;
    y = fmaxf(y, -120.0f);
    float n = floorf(y);
    float f = y - n;
    float p = 1.5403530393381606e-4f;
    p = fmaf(p, f, 1.3333558146428443e-3f);
    p = fmaf(p, f, 9.6181291076284771e-3f);
    p = fmaf(p, f, 5.5504108664821580e-2f);
    p = fmaf(p, f, 2.4022650695910071e-1f);
    p = fmaf(p, f, 6.9314718055994531e-1f);
    p = fmaf(p, f, 1.0f);
    float r = __int_as_float(((int)n + 127) << 23);
    return p * r;
}

__device__ __forceinline__ void mma_bf16(float* c, const uint32_t* a, uint32_t b0, uint32_t b1) {
    asm volatile(
        "mma.sync.aligned.m16n8k16.row.col.f32.bf16.bf16.f32 "
        "{%0,%1,%2,%3}, {%4,%5,%6,%7}, {%8,%9}, {%0,%1,%2,%3};"
        : "+f"(c[0]), "+f"(c[1]), "+f"(c[2]), "+f"(c[3])
        : "r"(a[0]), "r"(a[1]), "r"(a[2]), "r"(a[3]), "r"(b0), "r"(b1));
}

__device__ __forceinline__ void cp16(void* dst, const void* src) {
    uint32_t d = (uint32_t)__cvta_generic_to_shared(dst);
    asm volatile("cp.async.cg.shared.global [%0], [%1], 16;" :: "r"(d), "l"(src));
}
#define CP_COMMIT()  asm volatile("cp.async.commit_group;")
#define CP_WAIT(N)   asm volatile("cp.async.wait_group %0;" :: "n"(N))

// ---------------- bf16 split kernel ----------------
__global__ void split_kernel(const float* __restrict__ src,
                             __nv_bfloat16* __restrict__ hi,
                             __nv_bfloat16* __restrict__ lo, int n) {
    int i = (blockIdx.x * blockDim.x + threadIdx.x) * 4;
    if (i < n) {
        float4 v = *(const float4*)(src + i);
        uint32_t h0, l0, h1, l1;
        split2(v.x, v.y, h0, l0);
        split2(v.z, v.w, h1, l1);
        *(uint2*)(hi + i) = make_uint2(h0, h1);
        *(uint2*)(lo + i) = make_uint2(l0, l1);
    }
}

// ---------------- projection GEMM (bf16x3, mma.sync) ----------------
// C[M,N] = A[M,K] * W[N,K]^T + bias, bf16x3.
// BM=BN=128, BK=32, 256 threads, warp tile 64x32.
// MODE 0: fp32 flat [M,DMODEL];  MODE 1: bf16 hi/lo [B,H,T,dk];  MODE 2: bf16 hi/lo [B,H,dk,T]
#define PJ_TB   (128 * 40)         // padded tile elems per tensor per buffer
#define PJ_SMEM (4 * 2 * PJ_TB * 2)

template <int MODE>
__global__ __launch_bounds__(256) void proj_mma(
    const __nv_bfloat16* __restrict__ Ahi, const __nv_bfloat16* __restrict__ Alo,
    const __nv_bfloat16* __restrict__ Bhi, const __nv_bfloat16* __restrict__ Blo,
    const float* __restrict__ bias,
    float* __restrict__ outF,
    __nv_bfloat16* __restrict__ outHi, __nv_bfloat16* __restrict__ outLo)
{
    extern __shared__ __align__(16) unsigned char smem_raw[];
    __nv_bfloat16* sA_hi = (__nv_bfloat16*)smem_raw;
    __nv_bfloat16* sA_lo = sA_hi + 2 * PJ_TB;
    __nv_bfloat16* sB_hi = sA_lo + 2 * PJ_TB;
    __nv_bfloat16* sB_lo = sB_hi + 2 * PJ_TB;

    const int tid = threadIdx.x;
    const int lane = tid & 31, wid = tid >> 5;
    const int wm = wid >> 2, wn = wid & 3;      // 2 x 4 warps
    const int m0 = blockIdx.y * 128, n0 = blockIdx.x * 128;
    const int g = lane >> 2;
    const int ke = (lane & 3);                  // u32 column unit within k16

    const int lrow = tid >> 2;                  // 0..63
    const int lch  = (tid & 3) * 8;             // elem offset of 16B chunk

    float acc[4][4][4];
#pragma unroll
    for (int a = 0; a < 4; a++)
#pragma unroll
        for (int b = 0; b < 4; b++)
#pragma unroll
            for (int c = 0; c < 4; c++) acc[a][b][c] = 0.0f;

    auto load_stage = [&](int s, int buf) {
        int k0 = s * 32;
        const __nv_bfloat16* ga_h = Ahi + (size_t)m0 * KDIM + k0;
        const __nv_bfloat16* ga_l = Alo + (size_t)m0 * KDIM + k0;
        const __nv_bfloat16* gb_h = Bhi + (size_t)n0 * KDIM + k0;
        const __nv_bfloat16* gb_l = Blo + (size_t)n0 * KDIM + k0;
#pragma unroll
        for (int i = 0; i < 2; i++) {
            int r = lrow + i * 64;
            int se = r * 40 + lch;
            size_t ge = (size_t)r * KDIM + lch;
            cp16(sA_hi + buf * PJ_TB + se, ga_h + ge);
            cp16(sA_lo + buf * PJ_TB + se, ga_l + ge);
            cp16(sB_hi + buf * PJ_TB + se, gb_h + ge);
            cp16(sB_lo + buf * PJ_TB + se, gb_l + ge);
        }
    };

    load_stage(0, 0);
    CP_COMMIT();

    const int NS = KDIM / 32;
    for (int s = 0; s < NS; s++) {
        if (s + 1 < NS) { load_stage(s + 1, (s + 1) & 1); CP_COMMIT(); CP_WAIT(1); }
        else            { CP_WAIT(0); }
        __syncthreads();

        const int buf = s & 1;
        const uint32_t* uAh = (const uint32_t*)(sA_hi + buf * PJ_TB);
        const uint32_t* uAl = (const uint32_t*)(sA_lo + buf * PJ_TB);
        const uint32_t* uBh = (const uint32_t*)(sB_hi + buf * PJ_TB);
        const uint32_t* uBl = (const uint32_t*)(sB_lo + buf * PJ_TB);

#pragma unroll
        for (int kk = 0; kk < 2; kk++) {
            const int colu = kk * 8 + ke;
            uint32_t ah[4][4], al[4][4];
#pragma unroll
            for (int mt = 0; mt < 4; mt++) {
                int r = wm * 64 + mt * 16 + g;
                int o0 = r * 20 + colu;
                ah[mt][0] = uAh[o0];            ah[mt][1] = uAh[o0 + 160];
                ah[mt][2] = uAh[o0 + 4];        ah[mt][3] = uAh[o0 + 164];
                al[mt][0] = uAl[o0];            al[mt][1] = uAl[o0 + 160];
                al[mt][2] = uAl[o0 + 4];        al[mt][3] = uAl[o0 + 164];
            }
            uint32_t bh[4][2], bl[4][2];
#pragma unroll
            for (int nt = 0; nt < 4; nt++) {
                int r = wn * 32 + nt * 8 + g;
                int o0 = r * 20 + colu;
                bh[nt][0] = uBh[o0];  bh[nt][1] = uBh[o0 + 4];
                bl[nt][0] = uBl[o0];  bl[nt][1] = uBl[o0 + 4];
            }
#pragma unroll
            for (int mt = 0; mt < 4; mt++)
#pragma unroll
                for (int nt = 0; nt < 4; nt++) {
                    mma_bf16(acc[mt][nt], ah[mt], bh[nt][0], bh[nt][1]);
                    mma_bf16(acc[mt][nt], ah[mt], bl[nt][0], bl[nt][1]);
                    mma_bf16(acc[mt][nt], al[mt], bh[nt][0], bh[nt][1]);
                }
        }
        __syncthreads();
    }

    // epilogue
#pragma unroll
    for (int mt = 0; mt < 4; mt++) {
#pragma unroll
        for (int nt = 0; nt < 4; nt++) {
            int r = m0 + wm * 64 + mt * 16 + g;
            int c = n0 + wn * 32 + nt * 8 + (lane & 3) * 2;
            float bx = bias[c], by = bias[c + 1];
            float v00 = acc[mt][nt][0] + bx, v01 = acc[mt][nt][1] + by;
            float v10 = acc[mt][nt][2] + bx, v11 = acc[mt][nt][3] + by;
            if (MODE == 0) {
                *(float2*)(outF + (size_t)r * DMODEL + c)       = make_float2(v00, v01);
                *(float2*)(outF + (size_t)(r + 8) * DMODEL + c) = make_float2(v10, v11);
            } else if (MODE == 1) {
                int b_ = r >> 11, hh = c >> 6, d = c & 63;
                int t0 = r & 2047;
                size_t d0 = (((size_t)(b_ * NHEAD + hh) * T_DIM + t0) * DKH) + d;
                size_t d1 = (((size_t)(b_ * NHEAD + hh) * T_DIM + t0 + 8) * DKH) + d;
                uint32_t hi, lo;
                split2(v00, v01, hi, lo);
                *(uint32_t*)(outHi + d0) = hi; *(uint32_t*)(outLo + d0) = lo;
                split2(v10, v11, hi, lo);
                *(uint32_t*)(outHi + d1) = hi; *(uint32_t*)(outLo + d1) = lo;
            } else {
                int b_ = r >> 11, hh = c >> 6, d = c & 63;
                int t0 = r & 2047;
                size_t base = ((size_t)(b_ * NHEAD + hh) * DKH + d) * T_DIM;
                __nv_bfloat16 h;
                h = __float2bfloat16_rn(v00); outHi[base + t0] = h;
                outLo[base + t0] = __float2bfloat16_rn(v00 - __bfloat162float(h));
                h = __float2bfloat16_rn(v01); outHi[base + T_DIM + t0] = h;
                outLo[base + T_DIM + t0] = __float2bfloat16_rn(v01 - __bfloat162float(h));
                h = __float2bfloat16_rn(v10); outHi[base + t0 + 8] = h;
                outLo[base + t0 + 8] = __float2bfloat16_rn(v10 - __bfloat162float(h));
                h = __float2bfloat16_rn(v11); outHi[base + T_DIM + t0 + 8] = h;
                outLo[base + T_DIM + t0 + 8] = __float2bfloat16_rn(v11 - __bfloat162float(h));
            }
        }
    }
}

// ---------------- flash attention (bf16x3, mma.sync) ----------------
// CTA: 128 q-rows, 8 warps (16 rows each), loops over 32 key-chunks of 64.
#define FL_KT   (64 * 72)          // padded tile elems per tensor per buffer
#define FL_SMEM (4 * 2 * FL_KT * 2)

__global__ __launch_bounds__(256) void flash_mma(
    const float* __restrict__ bias,
    const __nv_bfloat16* __restrict__ Qhi, const __nv_bfloat16* __restrict__ Qlo,
    const __nv_bfloat16* __restrict__ Khi, const __nv_bfloat16* __restrict__ Klo,
    const __nv_bfloat16* __restrict__ Vhi, const __nv_bfloat16* __restrict__ Vlo,
    __nv_bfloat16* __restrict__ Ohi, __nv_bfloat16* __restrict__ Olo)
{
    extern __shared__ __align__(16) unsigned char smem_raw[];
    __nv_bfloat16* sK_hi = (__nv_bfloat16*)smem_raw;
    __nv_bfloat16* sK_lo = sK_hi + 2 * FL_KT;
    __nv_bfloat16* sV_hi = sK_lo + 2 * FL_KT;
    __nv_bfloat16* sV_lo = sV_hi + 2 * FL_KT;

    const int tid = threadIdx.x;
    const int lane = tid & 31, wid = tid >> 5;
    const int q0 = blockIdx.x * 128;
    const int h  = blockIdx.y;
    const int b  = blockIdx.z;
    const size_t bh = (size_t)b * NHEAD + h;

    const __nv_bfloat16* qh = Qhi + bh * T_DIM * DKH;
    const __nv_bfloat16* ql = Qlo + bh * T_DIM * DKH;
    const __nv_bfloat16* kh = Khi + bh * T_DIM * DKH;
    const __nv_bfloat16* kl = Klo + bh * T_DIM * DKH;
    const __nv_bfloat16* vh = Vhi + bh * DKH * T_DIM;
    const __nv_bfloat16* vl = Vlo + bh * DKH * T_DIM;
    const float* bp = bias + (size_t)h * T_DIM * T_DIM;

    const int g  = lane >> 2;
    const int ke = (lane & 3) * 2;     // element col offset
    const int qr = q0 + wid * 16 + g;  // this lane's first q row

    // Q fragments (held in registers for the whole kernel)
    uint32_t qAh[4][4], qAl[4][4];
#pragma unroll
    for (int kt = 0; kt < 4; kt++) {
        size_t base = (size_t)qr * DKH + kt * 16 + ke;
        qAh[kt][0] = *(const uint32_t*)(qh + base);
        qAh[kt][1] = *(const uint32_t*)(qh + base + 8 * DKH);
        qAh[kt][2] = *(const uint32_t*)(qh + base + 8);
        qAh[kt][3] = *(const uint32_t*)(qh + base + 8 * DKH + 8);
        qAl[kt][0] = *(const uint32_t*)(ql + base);
        qAl[kt][1] = *(const uint32_t*)(ql + base + 8 * DKH);
        qAl[kt][2] = *(const uint32_t*)(ql + base + 8);
        qAl[kt][3] = *(const uint32_t*)(ql + base + 8 * DKH + 8);
    }

    float m0r = -1e30f, m1r = -1e30f, l0r = 0.0f, l1r = 0.0f;
    float o[8][4];
#pragma unroll
    for (int i = 0; i < 8; i++)
#pragma unroll
        for (int j = 0; j < 4; j++) o[i][j] = 0.0f;

    const int lrow = tid >> 3;          // 0..31
    const int lch  = (tid & 7) * 8;     // elem offset of 16B chunk

    auto load_chunk = [&](int c, int buf) {
        int k0 = c * 64;
#pragma unroll
        for (int i = 0; i < 2; i++) {
            int r = lrow + i * 32;
            int se = r * 72 + lch;
            cp16(sK_hi + buf * FL_KT + se, kh + (size_t)(k0 + r) * DKH + lch);
            cp16(sK_lo + buf * FL_KT + se, kl + (size_t)(k0 + r) * DKH + lch);
            cp16(sV_hi + buf * FL_KT + se, vh + (size_t)r * T_DIM + k0 + lch);
            cp16(sV_lo + buf * FL_KT + se, vl + (size_t)r * T_DIM + k0 + lch);
        }
    };

    load_chunk(0, 0);
    CP_COMMIT();

    const int NCH = T_DIM / 64;
    for (int c = 0; c < NCH; c++) {
        if (c + 1 < NCH) { load_chunk(c + 1, (c + 1) & 1); CP_COMMIT(); CP_WAIT(1); }
        else             { CP_WAIT(0); }
        __syncthreads();

        const int buf = c & 1;
        const int k0 = c * 64;
        const uint32_t* uKh = (const uint32_t*)(sK_hi + buf * FL_KT);
        const uint32_t* uKl = (const uint32_t*)(sK_lo + buf * FL_KT);
        const uint32_t* uVh = (const uint32_t*)(sV_hi + buf * FL_KT);
        const uint32_t* uVl = (const uint32_t*)(sV_lo + buf * FL_KT);

        // ---- S = Q K^T (bf16x3) ----
        float s[8][4];
#pragma unroll
        for (int i = 0; i < 8; i++)
#pragma unroll
            for (int j = 0; j < 4; j++) s[i][j] = 0.0f;

#pragma unroll
        for (int kt = 0; kt < 4; kt++) {
            const int colu = kt * 8 + (lane & 3);
#pragma unroll
            for (int nt = 0; nt < 8; nt++) {
                int o0 = (nt * 8 + g) * 36 + colu;
                uint32_t bh0 = uKh[o0], bh1 = uKh[o0 + 4];
                uint32_t bl0 = uKl[o0], bl1 = uKl[o0 + 4];
                mma_bf16(s[nt], qAh[kt], bh0, bh1);
                mma_bf16(s[nt], qAh[kt], bl0, bl1);
                mma_bf16(s[nt], qAl[kt], bh0, bh1);
            }
        }

        // ---- scale + bias ----
#pragma unroll
        for (int nt = 0; nt < 8; nt++) {
            const float* bb = bp + (size_t)qr * T_DIM + k0 + nt * 8 + ke;
            float2 b0 = *(const float2*)bb;
            float2 b1 = *(const float2*)(bb + 8 * T_DIM);
            s[nt][0] = fmaf(s[nt][0], 0.125f, b0.x);
            s[nt][1] = fmaf(s[nt][1], 0.125f, b0.y);
            s[nt][2] = fmaf(s[nt][2], 0.125f, b1.x);
            s[nt][3] = fmaf(s[nt][3], 0.125f, b1.y);
        }

        // ---- online softmax (quad shfl reduction) ----
        float t0 = -1e30f, t1 = -1e30f;
#pragma unroll
        for (int nt = 0; nt < 8; nt++) {
            t0 = fmaxf(t0, fmaxf(s[nt][0], s[nt][1]));
            t1 = fmaxf(t1, fmaxf(s[nt][2], s[nt][3]));
        }
        t0 = fmaxf(t0, __shfl_xor_sync(0xffffffffu, t0, 1));
        t0 = fmaxf(t0, __shfl_xor_sync(0xffffffffu, t0, 2));
        t1 = fmaxf(t1, __shfl_xor_sync(0xffffffffu, t1, 1));
        t1 = fmaxf(t1, __shfl_xor_sync(0xffffffffu, t1, 2));
        float nm0 = fmaxf(m0r, t0), nm1 = fmaxf(m1r, t1);
        float al0 = fexp(m0r - nm0), al1 = fexp(m1r - nm1);
        m0r = nm0; m1r = nm1;

        float sum0 = 0.0f, sum1 = 0.0f;
#pragma unroll
        for (int nt = 0; nt < 8; nt++) {
            s[nt][0] = fexp(s[nt][0] - nm0); sum0 += s[nt][0];
            s[nt][1] = fexp(s[nt][1] - nm0); sum0 += s[nt][1];
            s[nt][2] = fexp(s[nt][2] - nm1); sum1 += s[nt][2];
            s[nt][3] = fexp(s[nt][3] - nm1); sum1 += s[nt][3];
        }
        sum0 += __shfl_xor_sync(0xffffffffu, sum0, 1);
        sum0 += __shfl_xor_sync(0xffffffffu, sum0, 2);
        sum1 += __shfl_xor_sync(0xffffffffu, sum1, 1);
        sum1 += __shfl_xor_sync(0xffffffffu, sum1, 2);
        l0r = l0r * al0 + sum0;
        l1r = l1r * al1 + sum1;

#pragma unroll
        for (int nt = 0; nt < 8; nt++) {
            o[nt][0] *= al0; o[nt][1] *= al0;
            o[nt][2] *= al1; o[nt][3] *= al1;
        }

        // ---- O += P V (bf16x3, P passed register->register) ----
#pragma unroll
        for (int kt = 0; kt < 4; kt++) {
            const int e = 2 * kt;
            uint32_t pAh[4], pAl[4];
            split2(s[e][0],     s[e][1],     pAh[0], pAl[0]);
            split2(s[e][2],     s[e][3],     pAh[1], pAl[1]);
            split2(s[e + 1][0], s[e + 1][1], pAh[2], pAl[2]);
            split2(s[e + 1][2], s[e + 1][3], pAh[3], pAl[3]);
            const int colu = kt * 8 + (lane & 3);
#pragma unroll
            for (int nt = 0; nt < 8; nt++) {
                int o0 = (nt * 8 + g) * 36 + colu;
                uint32_t vh0 = uVh[o0], vh1 = uVh[o0 + 4];
                uint32_t vl0 = uVl[o0], vl1 = uVl[o0 + 4];
                mma_bf16(o[nt], pAh, vh0, vh1);
                mma_bf16(o[nt], pAh, vl0, vl1);
                mma_bf16(o[nt], pAl, vh0, vh1);
            }
        }
        __syncthreads();
    }

    // ---- epilogue: O /= l, write bf16 hi/lo into [B,T,D] ----
    float i0 = __fdividef(1.0f, l0r), i1 = __fdividef(1.0f, l1r);
#pragma unroll
    for (int nt = 0; nt < 8; nt++) {
        float v00 = o[nt][0] * i0, v01 = o[nt][1] * i0;
        float v10 = o[nt][2] * i1, v11 = o[nt][3] * i1;
        int d = h * DKH + nt * 8 + ke;
        size_t d0 = ((size_t)(b * T_DIM + qr)) * DMODEL + d;
        size_t d1 = ((size_t)(b * T_DIM + qr + 8)) * DMODEL + d;
        uint32_t hi, lo;
        split2(v00, v01, hi, lo);
        *(uint32_t*)(Ohi + d0) = hi; *(uint32_t*)(Olo + d0) = lo;
        split2(v10, v11, hi, lo);
        *(uint32_t*)(Ohi + d1) = hi; *(uint32_t*)(Olo + d1) = lo;
    }
}

// ---------------- launch ----------------
extern "C" void kernel_launch(void* const* d_in, const int* in_sizes, int n_in,
                              void* d_out, int out_size)
{
    const float* x    = (const float*)d_in[0];
    const float* bias = (const float*)d_in[1];
    const float* Wq   = (const float*)d_in[2];
    const float* bq   = (const float*)d_in[3];
    const float* Wk   = (const float*)d_in[4];
    const float* bk   = (const float*)d_in[5];
    const float* Wv   = (const float*)d_in[6];
    const float* bv   = (const float*)d_in[7];
    const float* Wo   = (const float*)d_in[8];
    const float* bo   = (const float*)d_in[9];
    float* out = (float*)d_out;

    __nv_bfloat16 *xhi, *xlo, *whi, *wlo, *qhi, *qlo, *khi, *klo, *vhi, *vlo, *ahi, *alo;
    cudaGetSymbolAddress((void**)&xhi, g_xhi); cudaGetSymbolAddress((void**)&xlo, g_xlo);
    cudaGetSymbolAddress((void**)&whi, g_whi); cudaGetSymbolAddress((void**)&wlo, g_wlo);
    cudaGetSymbolAddress((void**)&qhi, g_qhi); cudaGetSymbolAddress((void**)&qlo, g_qlo);
    cudaGetSymbolAddress((void**)&khi, g_khi); cudaGetSymbolAddress((void**)&klo, g_klo);
    cudaGetSymbolAddress((void**)&vhi, g_vhi); cudaGetSymbolAddress((void**)&vlo, g_vlo);
    cudaGetSymbolAddress((void**)&ahi, g_ahi); cudaGetSymbolAddress((void**)&alo, g_alo);

    static bool attr_done = false;
    if (!attr_done) {
        cudaFuncSetAttribute(proj_mma<0>, cudaFuncAttributeMaxDynamicSharedMemorySize, PJ_SMEM);
        cudaFuncSetAttribute(proj_mma<1>, cudaFuncAttributeMaxDynamicSharedMemorySize, PJ_SMEM);
        cudaFuncSetAttribute(proj_mma<2>, cudaFuncAttributeMaxDynamicSharedMemorySize, PJ_SMEM);
        cudaFuncSetAttribute(flash_mma,   cudaFuncAttributeMaxDynamicSharedMemorySize, FL_SMEM);
        attr_done = true;
    }

    const int WN = DMODEL * DMODEL;  // 1M

    // bf16 splits
    split_kernel<<<M_DIM * DMODEL / 1024, 256>>>(x, xhi, xlo, M_DIM * DMODEL);
    split_kernel<<<WN / 1024, 256>>>(Wq, whi + 0 * WN, wlo + 0 * WN, WN);
    split_kernel<<<WN / 1024, 256>>>(Wk, whi + 1 * WN, wlo + 1 * WN, WN);
    split_kernel<<<WN / 1024, 256>>>(Wv, whi + 2 * WN, wlo + 2 * WN, WN);
    split_kernel<<<WN / 1024, 256>>>(Wo, whi + 3 * WN, wlo + 3 * WN, WN);

    dim3 gg(DMODEL / 128, M_DIM / 128);  // (8, 32)
    proj_mma<1><<<gg, 256, PJ_SMEM>>>(xhi, xlo, whi + 0 * WN, wlo + 0 * WN, bq,
                                      nullptr, qhi, qlo);
    proj_mma<1><<<gg, 256, PJ_SMEM>>>(xhi, xlo, whi + 1 * WN, wlo + 1 * WN, bk,
                                      nullptr, khi, klo);
    proj_mma<2><<<gg, 256, PJ_SMEM>>>(xhi, xlo, whi + 2 * WN, wlo + 2 * WN, bv,
                                      nullptr, vhi, vlo);

    flash_mma<<<dim3(T_DIM / 128, NHEAD, B_DIM), 256, FL_SMEM>>>(
        bias, qhi, qlo, khi, klo, vhi, vlo, ahi, alo);

    proj_mma<0><<<gg, 256, PJ_SMEM>>>(ahi, alo, whi + 3 * WN, wlo + 3 * WN, bo,
                                      out, nullptr, nullptr);
}